// round 1
// baseline (speedup 1.0000x reference)
#include <cuda_runtime.h>
#include <math.h>

// ---------------- problem constants ----------------
#define BATCH   32
#define HW      56
#define DIM     256
#define WS      7
#define SHIFT   3
#define NH      8
#define HD      32
#define NTOK    49            // tokens per window
#define NWIN    64            // windows per image (8x8)
#define BW      (BATCH*NWIN)  // 2048
#define MTOK    (BATCH*HW*HW) // 100352 rows
#define SCALE   0.17677669529663687f   // 32^-0.5

// ---------------- scratch (static device globals; allocation-free) ----------
__device__ float g_xw  [(size_t)MTOK * 256];   // LN1 out (window order) -> attn out -> LN2 out
__device__ float g_qkv [(size_t)MTOK * 768];
__device__ float g_xres[(size_t)MTOK * 256];   // x + attn branch
__device__ float g_h1  [(size_t)MTOK * 1024];  // fc1 output
__device__ float g_bias[NH * NTOK * NTOK];     // rel-pos bias (8,49,49)

// ---------------- relative position bias ----------------
__global__ void bias_kernel(const float* __restrict__ rel_table, float* __restrict__ bias)
{
    int i = blockIdx.x * 256 + threadIdx.x;
    if (i >= NH * NTOK * NTOK) return;
    int h = i / (NTOK*NTOK), rem = i % (NTOK*NTOK);
    int n = rem / NTOK, m = rem % NTOK;
    int rn = n / 7, cn = n % 7, rm = m / 7, cm = m % 7;
    int idx = (rn - rm + 6) * 13 + (cn - cm + 6);
    bias[i] = rel_table[idx * NH + h];
}

// ---------------- LayerNorm (one row per block, 256 threads) ----------------
// PERM=1: read from x with cyclic shift + window partition (dst in window order)
// PERM=0: identity row mapping
template<int PERM>
__global__ void __launch_bounds__(256) ln_kernel(
    const float* __restrict__ in, float* __restrict__ out,
    const float* __restrict__ gam, const float* __restrict__ bet)
{
    int row = blockIdx.x;
    int src;
    if (PERM) {
        int bw = row / NTOK, t = row % NTOK;
        int b = bw >> 6, w = bw & 63;
        int wh = w >> 3, ww = w & 7;
        int r = t / 7, c = t % 7;
        int gh = wh * 7 + r + SHIFT; if (gh >= HW) gh -= HW;
        int gw = ww * 7 + c + SHIFT; if (gw >= HW) gw -= HW;
        src = (b * (HW*HW) + gh * HW + gw) * DIM;
    } else {
        src = row * DIM;
    }
    int dst = row * DIM;
    int tid = threadIdx.x;
    float val = in[src + tid];

    float s = val, q = val * val;
    #pragma unroll
    for (int o = 16; o > 0; o >>= 1) {
        s += __shfl_down_sync(0xFFFFFFFFu, s, o);
        q += __shfl_down_sync(0xFFFFFFFFu, q, o);
    }
    __shared__ float rs[8], rq[8];
    __shared__ float smu, srstd;
    int wid = tid >> 5, lane = tid & 31;
    if (lane == 0) { rs[wid] = s; rq[wid] = q; }
    __syncthreads();
    if (tid == 0) {
        float S = 0.f, Q = 0.f;
        #pragma unroll
        for (int i = 0; i < 8; i++) { S += rs[i]; Q += rq[i]; }
        float mu = S * (1.0f/DIM);
        smu = mu;
        srstd = rsqrtf(Q * (1.0f/DIM) - mu*mu + 1e-5f);
    }
    __syncthreads();
    out[dst + tid] = (val - smu) * srstd * gam[tid] + bet[tid];
}

// ---------------- SGEMM: C[M,N] = A[M,K] @ B[N,K]^T + bias, with epilogues --
// EPI 0: qkv  (scale q columns n<256)
// EPI 1: fc1  (exact gelu)
// EPI 2: proj (window reverse + roll(+3) + residual from res=x)
// EPI 3: fc2  (residual from res=g_xres)
#define BM 128
#define BN 64
#define BKk 16

template<int EPI>
__global__ void __launch_bounds__(256) sgemm_kernel(
    const float* __restrict__ A, const float* __restrict__ B,
    const float* __restrict__ bias, float* __restrict__ C,
    const float* __restrict__ res, int M, int Nn, int K)
{
    __shared__ float As[BKk][BM + 4];
    __shared__ float Bs[BKk][BN + 4];

    const int tid = threadIdx.x;
    const int tx = tid & 15;   // N dim, 4 cols each
    const int ty = tid >> 4;   // M dim, 8 rows each
    const int m0 = blockIdx.y * BM;
    const int n0 = blockIdx.x * BN;

    float acc[8][4];
    #pragma unroll
    for (int i = 0; i < 8; i++)
        #pragma unroll
        for (int j = 0; j < 4; j++) acc[i][j] = 0.f;

    const int lrow = tid >> 2;          // 0..63
    const int lkq  = (tid & 3) * 4;     // 0,4,8,12

    for (int kt = 0; kt < K; kt += BKk) {
        #pragma unroll
        for (int p = 0; p < 2; p++) {
            int row = lrow + p * 64;
            float4 a = *(const float4*)&A[(size_t)(m0 + row) * K + kt + lkq];
            As[lkq+0][row] = a.x; As[lkq+1][row] = a.y;
            As[lkq+2][row] = a.z; As[lkq+3][row] = a.w;
        }
        {
            float4 b = *(const float4*)&B[(size_t)(n0 + lrow) * K + kt + lkq];
            Bs[lkq+0][lrow] = b.x; Bs[lkq+1][lrow] = b.y;
            Bs[lkq+2][lrow] = b.z; Bs[lkq+3][lrow] = b.w;
        }
        __syncthreads();
        #pragma unroll
        for (int kk = 0; kk < BKk; kk++) {
            float4 a0 = *(const float4*)&As[kk][ty*8];
            float4 a1 = *(const float4*)&As[kk][ty*8+4];
            float4 b0 = *(const float4*)&Bs[kk][tx*4];
            float av[8] = {a0.x,a0.y,a0.z,a0.w,a1.x,a1.y,a1.z,a1.w};
            float bv[4] = {b0.x,b0.y,b0.z,b0.w};
            #pragma unroll
            for (int i = 0; i < 8; i++)
                #pragma unroll
                for (int j = 0; j < 4; j++)
                    acc[i][j] = fmaf(av[i], bv[j], acc[i][j]);
        }
        __syncthreads();
    }

    const int nbase = n0 + tx * 4;
    float4 bs = *(const float4*)&bias[nbase];

    #pragma unroll
    for (int i = 0; i < 8; i++) {
        int m = m0 + ty * 8 + i;
        float v0 = acc[i][0] + bs.x;
        float v1 = acc[i][1] + bs.y;
        float v2 = acc[i][2] + bs.z;
        float v3 = acc[i][3] + bs.w;

        if (EPI == 0) {
            if (nbase < 256) { v0 *= SCALE; v1 *= SCALE; v2 *= SCALE; v3 *= SCALE; }
            *(float4*)&C[(size_t)m * Nn + nbase] = make_float4(v0, v1, v2, v3);
        } else if (EPI == 1) {
            const float k = 0.70710678118654752f;
            v0 = 0.5f * v0 * (1.f + erff(v0 * k));
            v1 = 0.5f * v1 * (1.f + erff(v1 * k));
            v2 = 0.5f * v2 * (1.f + erff(v2 * k));
            v3 = 0.5f * v3 * (1.f + erff(v3 * k));
            *(float4*)&C[(size_t)m * Nn + nbase] = make_float4(v0, v1, v2, v3);
        } else if (EPI == 2) {
            int bw = m / NTOK, t = m % NTOK;
            int b = bw >> 6, w = bw & 63;
            int wh = w >> 3, ww = w & 7;
            int r = t / 7, c = t % 7;
            int gh = wh * 7 + r + SHIFT; if (gh >= HW) gh -= HW;
            int gw = ww * 7 + c + SHIFT; if (gw >= HW) gw -= HW;
            size_t dst = (size_t)(b * (HW*HW) + gh * HW + gw) * DIM + nbase;
            float4 rr = *(const float4*)&res[dst];
            *(float4*)&C[dst] = make_float4(v0 + rr.x, v1 + rr.y, v2 + rr.z, v3 + rr.w);
        } else { // EPI == 3
            size_t dst = (size_t)m * Nn + nbase;
            float4 rr = *(const float4*)&res[dst];
            *(float4*)&C[dst] = make_float4(v0 + rr.x, v1 + rr.y, v2 + rr.z, v3 + rr.w);
        }
    }
}

// ---------------- attention: one block per (window, head) -------------------
__global__ void __launch_bounds__(256) attn_kernel(
    const float* __restrict__ qkv, const float* __restrict__ bias,
    float* __restrict__ out)
{
    __shared__ float sq[NTOK][33], sk[NTOK][33], sv[NTOK][33];
    __shared__ float sp[NTOK][50];
    __shared__ int   regn[NTOK];

    int bw = blockIdx.x >> 3;
    int h  = blockIdx.x & 7;
    int tid = threadIdx.x;

    if (tid < NTOK) {
        int w = bw & 63;
        int wh = w >> 3, ww = w & 7;
        int r = tid / 7, c = tid % 7;
        int gh = wh * 7 + r, gw = ww * 7 + c;
        int rh = (gh < HW - WS) ? 0 : ((gh < HW - SHIFT) ? 1 : 2);
        int rw = (gw < HW - WS) ? 0 : ((gw < HW - SHIFT) ? 1 : 2);
        regn[tid] = rh * 3 + rw;
    }
    for (int i = tid; i < NTOK * HD; i += 256) {
        int n = i >> 5, d = i & 31;
        size_t base = (size_t)(bw * NTOK + n) * 768 + h * HD + d;
        sq[n][d] = qkv[base];
        sk[n][d] = qkv[base + 256];
        sv[n][d] = qkv[base + 512];
    }
    __syncthreads();

    for (int s = tid; s < NTOK * NTOK; s += 256) {
        int n = s / NTOK, m = s % NTOK;
        float a = 0.f;
        #pragma unroll
        for (int d = 0; d < HD; d++) a = fmaf(sq[n][d], sk[m][d], a);
        a += bias[h * (NTOK*NTOK) + s];
        if (regn[n] != regn[m]) a -= 100.f;
        sp[n][m] = a;
    }
    __syncthreads();

    int wid = tid >> 5, lane = tid & 31;
    for (int r = wid; r < NTOK; r += 8) {
        float v0 = sp[r][lane];
        float v1 = (lane < NTOK - 32) ? sp[r][lane + 32] : -1e30f;
        float mx = fmaxf(v0, v1);
        #pragma unroll
        for (int o = 16; o > 0; o >>= 1) mx = fmaxf(mx, __shfl_xor_sync(0xFFFFFFFFu, mx, o));
        float e0 = __expf(v0 - mx);
        float e1 = (lane < NTOK - 32) ? __expf(v1 - mx) : 0.f;
        float sm = e0 + e1;
        #pragma unroll
        for (int o = 16; o > 0; o >>= 1) sm += __shfl_xor_sync(0xFFFFFFFFu, sm, o);
        float inv = 1.f / sm;
        sp[r][lane] = e0 * inv;
        if (lane < NTOK - 32) sp[r][lane + 32] = e1 * inv;
    }
    __syncthreads();

    for (int s = tid; s < NTOK * HD; s += 256) {
        int n = s >> 5, d = s & 31;
        float a = 0.f;
        #pragma unroll
        for (int m = 0; m < NTOK; m++) a = fmaf(sp[n][m], sv[m][d], a);
        out[(size_t)(bw * NTOK + n) * 256 + h * HD + d] = a;
    }
}

// ---------------- launcher ----------------
extern "C" void kernel_launch(void* const* d_in, const int* in_sizes, int n_in,
                              void* d_out, int out_size)
{
    (void)in_sizes; (void)n_in; (void)out_size;
    const float* x        = (const float*)d_in[0];
    const float* norm1_g  = (const float*)d_in[1];
    const float* norm1_b  = (const float*)d_in[2];
    const float* qkv_w    = (const float*)d_in[3];
    const float* qkv_b    = (const float*)d_in[4];
    const float* rel_tab  = (const float*)d_in[5];
    const float* proj_w   = (const float*)d_in[6];
    const float* proj_b   = (const float*)d_in[7];
    const float* norm2_g  = (const float*)d_in[8];
    const float* norm2_b  = (const float*)d_in[9];
    const float* fc1_w    = (const float*)d_in[10];
    const float* fc1_b    = (const float*)d_in[11];
    const float* fc2_w    = (const float*)d_in[12];
    const float* fc2_b    = (const float*)d_in[13];
    float* out = (float*)d_out;

    float *p_xw, *p_qkv, *p_xres, *p_h1, *p_bias;
    cudaGetSymbolAddress((void**)&p_xw,   g_xw);
    cudaGetSymbolAddress((void**)&p_qkv,  g_qkv);
    cudaGetSymbolAddress((void**)&p_xres, g_xres);
    cudaGetSymbolAddress((void**)&p_h1,   g_h1);
    cudaGetSymbolAddress((void**)&p_bias, g_bias);

    const int M = MTOK;

    // 1. relative position bias table expansion
    bias_kernel<<<(NH*NTOK*NTOK + 255)/256, 256>>>(rel_tab, p_bias);
    // 2. LN1 + shift + window partition
    ln_kernel<1><<<M, 256>>>(x, p_xw, norm1_g, norm1_b);
    // 3. QKV gemm (q scaled)
    sgemm_kernel<0><<<dim3(768/BN, M/BM), 256>>>(p_xw, qkv_w, qkv_b, p_qkv, nullptr, M, 768, 256);
    // 4. windowed attention (writes into g_xw, now free)
    attn_kernel<<<BW * NH, 256>>>(p_qkv, p_bias, p_xw);
    // 5. proj gemm + window reverse + unshift + residual
    sgemm_kernel<2><<<dim3(256/BN, M/BM), 256>>>(p_xw, proj_w, proj_b, p_xres, x, M, 256, 256);
    // 6. LN2 (g_xw reused as normalized activations)
    ln_kernel<0><<<M, 256>>>(p_xres, p_xw, norm2_g, norm2_b);
    // 7. fc1 + exact gelu
    sgemm_kernel<1><<<dim3(1024/BN, M/BM), 256>>>(p_xw, fc1_w, fc1_b, p_h1, nullptr, M, 1024, 256);
    // 8. fc2 + residual -> final output
    sgemm_kernel<3><<<dim3(256/BN, M/BM), 256>>>(p_h1, fc2_w, fc2_b, out, p_xres, M, 256, 1024);
}

// round 2
// speedup vs baseline: 1.9082x; 1.9082x over previous
#include <cuda_runtime.h>
#include <math.h>

// ---------------- problem constants ----------------
#define BATCH   32
#define HW      56
#define DIM     256
#define WS      7
#define SHIFT   3
#define NH      8
#define HD      32
#define NTOK    49
#define NWIN    64
#define BW      (BATCH*NWIN)
#define MTOK    (BATCH*HW*HW)   // 100352
#define SCALE   0.17677669529663687f

// ---------------- scratch ----------------
__device__ float g_xw  [(size_t)MTOK * 256];
__device__ float g_qkv [(size_t)MTOK * 768];
__device__ float g_xres[(size_t)MTOK * 256];
__device__ float g_h1  [(size_t)MTOK * 1024];
__device__ float g_bias[NH * NTOK * NTOK];

// ---------------- rel-pos bias ----------------
__global__ void bias_kernel(const float* __restrict__ rel_table, float* __restrict__ bias)
{
    int i = blockIdx.x * 256 + threadIdx.x;
    if (i >= NH * NTOK * NTOK) return;
    int h = i / (NTOK*NTOK), rem = i % (NTOK*NTOK);
    int n = rem / NTOK, m = rem % NTOK;
    int rn = n / 7, cn = n % 7, rm = m / 7, cm = m % 7;
    int idx = (rn - rm + 6) * 13 + (cn - cm + 6);
    bias[i] = rel_table[idx * NH + h];
}

// ---------------- LayerNorm ----------------
template<int PERM>
__global__ void __launch_bounds__(256) ln_kernel(
    const float* __restrict__ in, float* __restrict__ out,
    const float* __restrict__ gam, const float* __restrict__ bet)
{
    int row = blockIdx.x;
    int src;
    if (PERM) {
        int bw = row / NTOK, t = row % NTOK;
        int b = bw >> 6, w = bw & 63;
        int wh = w >> 3, ww = w & 7;
        int r = t / 7, c = t % 7;
        int gh = wh * 7 + r + SHIFT; if (gh >= HW) gh -= HW;
        int gw = ww * 7 + c + SHIFT; if (gw >= HW) gw -= HW;
        src = (b * (HW*HW) + gh * HW + gw) * DIM;
    } else {
        src = row * DIM;
    }
    int dst = row * DIM;
    int tid = threadIdx.x;
    float val = in[src + tid];

    float s = val, q = val * val;
    #pragma unroll
    for (int o = 16; o > 0; o >>= 1) {
        s += __shfl_down_sync(0xFFFFFFFFu, s, o);
        q += __shfl_down_sync(0xFFFFFFFFu, q, o);
    }
    __shared__ float rs[8], rq[8];
    __shared__ float smu, srstd;
    int wid = tid >> 5, lane = tid & 31;
    if (lane == 0) { rs[wid] = s; rq[wid] = q; }
    __syncthreads();
    if (tid == 0) {
        float S = 0.f, Q = 0.f;
        #pragma unroll
        for (int i = 0; i < 8; i++) { S += rs[i]; Q += rq[i]; }
        float mu = S * (1.0f/DIM);
        smu = mu;
        srstd = rsqrtf(Q * (1.0f/DIM) - mu*mu + 1e-5f);
    }
    __syncthreads();
    out[dst + tid] = (val - smu) * srstd * gam[tid] + bet[tid];
}

// ---------------- tf32 warp-MMA GEMM ----------------
// C[M,N] = A[M,K] @ B[N,K]^T + bias, epilogues as before.
// Block: 128M x 64N, BK=32. 8 warps: 4(M) x 2(N), warp tile 32x32.

__device__ __forceinline__ unsigned f2tf(float f) {
    unsigned u; asm("cvt.rna.tf32.f32 %0, %1;" : "=r"(u) : "f"(f)); return u;
}

__device__ __forceinline__ void mma_tf32(float* c, const unsigned* a, const unsigned* b) {
    asm("mma.sync.aligned.m16n8k8.row.col.f32.tf32.tf32.f32 "
        "{%0,%1,%2,%3},{%4,%5,%6,%7},{%8,%9},{%0,%1,%2,%3};"
        : "+f"(c[0]), "+f"(c[1]), "+f"(c[2]), "+f"(c[3])
        : "r"(a[0]), "r"(a[1]), "r"(a[2]), "r"(a[3]), "r"(b[0]), "r"(b[1]));
}

template<int EPI>
__global__ void __launch_bounds__(256) mma_gemm(
    const float* __restrict__ A, const float* __restrict__ B,
    const float* __restrict__ bias, float* __restrict__ C,
    const float* __restrict__ res, int M, int Nn, int K)
{
    __shared__ float As[128][36];
    __shared__ float Bs[64][36];

    const int tid = threadIdx.x;
    const int lane = tid & 31, wid = tid >> 5;
    const int wm = wid >> 1, wn = wid & 1;
    const int gid = lane >> 2, tig = lane & 3;
    const int m0 = blockIdx.y * 128, n0 = blockIdx.x * 64;

    float c[2][4][4];
    #pragma unroll
    for (int i = 0; i < 2; i++)
        #pragma unroll
        for (int j = 0; j < 4; j++)
            #pragma unroll
            for (int r = 0; r < 4; r++) c[i][j][r] = 0.f;

    float4 ar[4], br[2];

    // prefetch chunk 0
    #pragma unroll
    for (int i = 0; i < 4; i++) {
        int idx = tid + i * 256;
        int row = idx >> 3, c4 = (idx & 7) * 4;
        ar[i] = *(const float4*)&A[(size_t)(m0 + row) * K + c4];
    }
    #pragma unroll
    for (int i = 0; i < 2; i++) {
        int idx = tid + i * 256;
        int row = idx >> 3, c4 = (idx & 7) * 4;
        br[i] = *(const float4*)&B[(size_t)(n0 + row) * K + c4];
    }

    const int nk = K / 32;
    for (int kt = 0; kt < nk; kt++) {
        // store staged chunk
        #pragma unroll
        for (int i = 0; i < 4; i++) {
            int idx = tid + i * 256;
            int row = idx >> 3, c4 = (idx & 7) * 4;
            As[row][c4+0] = __uint_as_float(f2tf(ar[i].x));
            As[row][c4+1] = __uint_as_float(f2tf(ar[i].y));
            As[row][c4+2] = __uint_as_float(f2tf(ar[i].z));
            As[row][c4+3] = __uint_as_float(f2tf(ar[i].w));
        }
        #pragma unroll
        for (int i = 0; i < 2; i++) {
            int idx = tid + i * 256;
            int row = idx >> 3, c4 = (idx & 7) * 4;
            Bs[row][c4+0] = __uint_as_float(f2tf(br[i].x));
            Bs[row][c4+1] = __uint_as_float(f2tf(br[i].y));
            Bs[row][c4+2] = __uint_as_float(f2tf(br[i].z));
            Bs[row][c4+3] = __uint_as_float(f2tf(br[i].w));
        }
        __syncthreads();

        // prefetch next chunk (overlaps with compute)
        if (kt + 1 < nk) {
            int kb = (kt + 1) * 32;
            #pragma unroll
            for (int i = 0; i < 4; i++) {
                int idx = tid + i * 256;
                int row = idx >> 3, c4 = (idx & 7) * 4;
                ar[i] = *(const float4*)&A[(size_t)(m0 + row) * K + kb + c4];
            }
            #pragma unroll
            for (int i = 0; i < 2; i++) {
                int idx = tid + i * 256;
                int row = idx >> 3, c4 = (idx & 7) * 4;
                br[i] = *(const float4*)&B[(size_t)(n0 + row) * K + kb + c4];
            }
        }

        // compute 4 k-steps of 8
        #pragma unroll
        for (int kk = 0; kk < 4; kk++) {
            int kb = kk * 8;
            unsigned af[2][4], bf[4][2];
            #pragma unroll
            for (int mt = 0; mt < 2; mt++) {
                int rb = wm * 32 + mt * 16;
                af[mt][0] = __float_as_uint(As[rb + gid    ][kb + tig    ]);
                af[mt][1] = __float_as_uint(As[rb + gid + 8][kb + tig    ]);
                af[mt][2] = __float_as_uint(As[rb + gid    ][kb + tig + 4]);
                af[mt][3] = __float_as_uint(As[rb + gid + 8][kb + tig + 4]);
            }
            #pragma unroll
            for (int nt = 0; nt < 4; nt++) {
                int nb = wn * 32 + nt * 8;
                bf[nt][0] = __float_as_uint(Bs[nb + gid][kb + tig    ]);
                bf[nt][1] = __float_as_uint(Bs[nb + gid][kb + tig + 4]);
            }
            #pragma unroll
            for (int mt = 0; mt < 2; mt++)
                #pragma unroll
                for (int nt = 0; nt < 4; nt++)
                    mma_tf32(c[mt][nt], af[mt], bf[nt]);
        }
        __syncthreads();
    }

    // ---------------- epilogue ----------------
    #pragma unroll
    for (int mt = 0; mt < 2; mt++) {
        #pragma unroll
        for (int nt = 0; nt < 4; nt++) {
            int r0 = m0 + wm * 32 + mt * 16 + gid;
            int r1 = r0 + 8;
            int cb = n0 + wn * 32 + nt * 8 + 2 * tig;
            float bs0 = bias[cb], bs1 = bias[cb + 1];
            float v00 = c[mt][nt][0] + bs0, v01 = c[mt][nt][1] + bs1;
            float v10 = c[mt][nt][2] + bs0, v11 = c[mt][nt][3] + bs1;

            if (EPI == 0) {
                if (cb < 256) { v00 *= SCALE; v01 *= SCALE; v10 *= SCALE; v11 *= SCALE; }
                *(float2*)&C[(size_t)r0 * Nn + cb] = make_float2(v00, v01);
                *(float2*)&C[(size_t)r1 * Nn + cb] = make_float2(v10, v11);
            } else if (EPI == 1) {
                const float kk = 0.70710678118654752f;
                v00 = 0.5f * v00 * (1.f + erff(v00 * kk));
                v01 = 0.5f * v01 * (1.f + erff(v01 * kk));
                v10 = 0.5f * v10 * (1.f + erff(v10 * kk));
                v11 = 0.5f * v11 * (1.f + erff(v11 * kk));
                *(float2*)&C[(size_t)r0 * Nn + cb] = make_float2(v00, v01);
                *(float2*)&C[(size_t)r1 * Nn + cb] = make_float2(v10, v11);
            } else if (EPI == 2) {
                #pragma unroll
                for (int rr = 0; rr < 2; rr++) {
                    int m = rr ? r1 : r0;
                    float va = rr ? v10 : v00, vb = rr ? v11 : v01;
                    int bw = m / NTOK, t = m % NTOK;
                    int b = bw >> 6, w = bw & 63;
                    int wh = w >> 3, ww = w & 7;
                    int r = t / 7, cc = t % 7;
                    int gh = wh * 7 + r + SHIFT; if (gh >= HW) gh -= HW;
                    int gw = ww * 7 + cc + SHIFT; if (gw >= HW) gw -= HW;
                    size_t dst = (size_t)(b * (HW*HW) + gh * HW + gw) * DIM + cb;
                    float2 rv = *(const float2*)&res[dst];
                    *(float2*)&C[dst] = make_float2(va + rv.x, vb + rv.y);
                }
            } else { // EPI == 3
                size_t d0 = (size_t)r0 * Nn + cb, d1 = (size_t)r1 * Nn + cb;
                float2 ra = *(const float2*)&res[d0];
                float2 rb2 = *(const float2*)&res[d1];
                *(float2*)&C[d0] = make_float2(v00 + ra.x, v01 + ra.y);
                *(float2*)&C[d1] = make_float2(v10 + rb2.x, v11 + rb2.y);
            }
        }
    }
}

// ---------------- attention: one block per (window, head) -------------------
// warp-per-row QK^T with transposed K + fused softmax, then PV.
__global__ void __launch_bounds__(256) attn_kernel(
    const float* __restrict__ qkv, const float* __restrict__ bias,
    float* __restrict__ out)
{
    __shared__ float sq [NTOK][33];
    __shared__ float skT[HD][NTOK + 1];   // transposed K, stride 50 (odd stride mod 32)
    __shared__ float sv [NTOK][33];
    __shared__ float sp [NTOK][50];
    __shared__ int   regn[NTOK];

    int bw = blockIdx.x >> 3;
    int h  = blockIdx.x & 7;
    int tid = threadIdx.x, lane = tid & 31, wid = tid >> 5;

    if (tid < NTOK) {
        int w = bw & 63;
        int wh = w >> 3, ww = w & 7;
        int r = tid / 7, c = tid % 7;
        int gh = wh * 7 + r, gw = ww * 7 + c;
        int rh = (gh < HW - WS) ? 0 : ((gh < HW - SHIFT) ? 1 : 2);
        int rw = (gw < HW - WS) ? 0 : ((gw < HW - SHIFT) ? 1 : 2);
        regn[tid] = rh * 3 + rw;
    }
    for (int i = tid; i < NTOK * HD; i += 256) {
        int n = i >> 5, d = i & 31;
        size_t base = (size_t)(bw * NTOK + n) * 768 + h * HD + d;
        sq[n][d]  = qkv[base];
        skT[d][n] = qkv[base + 256];
        sv[n][d]  = qkv[base + 512];
    }
    __syncthreads();

    const float* brow = bias + h * (NTOK * NTOK);
    bool has1 = lane < (NTOK - 32);   // lanes 0..16 own second column m=lane+32
    int m1 = has1 ? lane + 32 : lane;

    for (int n = wid; n < NTOK; n += 8) {
        float a0 = 0.f, a1 = 0.f;
        #pragma unroll
        for (int d = 0; d < HD; d++) {
            float qd = sq[n][d];
            a0 = fmaf(qd, skT[d][lane], a0);
            a1 = fmaf(qd, skT[d][m1],   a1);
        }
        int rn = regn[n];
        a0 += brow[n * NTOK + lane] + ((rn != regn[lane]) ? -100.f : 0.f);
        if (has1) a1 += brow[n * NTOK + m1] + ((rn != regn[m1]) ? -100.f : 0.f);
        else      a1 = -1e30f;

        float mx = fmaxf(a0, a1);
        #pragma unroll
        for (int o = 16; o > 0; o >>= 1) mx = fmaxf(mx, __shfl_xor_sync(0xFFFFFFFFu, mx, o));
        float e0 = __expf(a0 - mx);
        float e1 = has1 ? __expf(a1 - mx) : 0.f;
        float sm = e0 + e1;
        #pragma unroll
        for (int o = 16; o > 0; o >>= 1) sm += __shfl_xor_sync(0xFFFFFFFFu, sm, o);
        float inv = 1.f / sm;
        sp[n][lane] = e0 * inv;
        if (has1) sp[n][lane + 32] = e1 * inv;
    }
    __syncthreads();

    for (int s = tid; s < NTOK * HD; s += 256) {
        int n = s >> 5, d = s & 31;
        float a = 0.f;
        #pragma unroll
        for (int m = 0; m < NTOK; m++) a = fmaf(sp[n][m], sv[m][d], a);
        out[(size_t)(bw * NTOK + n) * 256 + h * HD + d] = a;
    }
}

// ---------------- launcher ----------------
extern "C" void kernel_launch(void* const* d_in, const int* in_sizes, int n_in,
                              void* d_out, int out_size)
{
    (void)in_sizes; (void)n_in; (void)out_size;
    const float* x        = (const float*)d_in[0];
    const float* norm1_g  = (const float*)d_in[1];
    const float* norm1_b  = (const float*)d_in[2];
    const float* qkv_w    = (const float*)d_in[3];
    const float* qkv_b    = (const float*)d_in[4];
    const float* rel_tab  = (const float*)d_in[5];
    const float* proj_w   = (const float*)d_in[6];
    const float* proj_b   = (const float*)d_in[7];
    const float* norm2_g  = (const float*)d_in[8];
    const float* norm2_b  = (const float*)d_in[9];
    const float* fc1_w    = (const float*)d_in[10];
    const float* fc1_b    = (const float*)d_in[11];
    const float* fc2_w    = (const float*)d_in[12];
    const float* fc2_b    = (const float*)d_in[13];
    float* out = (float*)d_out;

    float *p_xw, *p_qkv, *p_xres, *p_h1, *p_bias;
    cudaGetSymbolAddress((void**)&p_xw,   g_xw);
    cudaGetSymbolAddress((void**)&p_qkv,  g_qkv);
    cudaGetSymbolAddress((void**)&p_xres, g_xres);
    cudaGetSymbolAddress((void**)&p_h1,   g_h1);
    cudaGetSymbolAddress((void**)&p_bias, g_bias);

    const int M = MTOK;

    bias_kernel<<<(NH*NTOK*NTOK + 255)/256, 256>>>(rel_tab, p_bias);
    ln_kernel<1><<<M, 256>>>(x, p_xw, norm1_g, norm1_b);
    mma_gemm<0><<<dim3(768/64, M/128), 256>>>(p_xw, qkv_w, qkv_b, p_qkv, nullptr, M, 768, 256);
    attn_kernel<<<BW * NH, 256>>>(p_qkv, p_bias, p_xw);
    mma_gemm<2><<<dim3(256/64, M/128), 256>>>(p_xw, proj_w, proj_b, p_xres, x, M, 256, 256);
    ln_kernel<0><<<M, 256>>>(p_xres, p_xw, norm2_g, norm2_b);
    mma_gemm<1><<<dim3(1024/64, M/128), 256>>>(p_xw, fc1_w, fc1_b, p_h1, nullptr, M, 1024, 256);
    mma_gemm<3><<<dim3(256/64, M/128), 256>>>(p_h1, fc2_w, fc2_b, out, p_xres, M, 256, 1024);
}